// round 14
// baseline (speedup 1.0000x reference)
#include <cuda_runtime.h>
#include <cuda_bf16.h>

// CapsuleModel2: sigmoid(segment_mean(feats[point_idx]) @ W + b)
// R14: project-then-pool + precomputed segment bounds.
//  K0: parallel boundary scan over sorted segment_ids -> g_bound[] (no search).
//  K1: 2 rows/thread register GEMM, KC=16 (40KB smem -> 4 CTAs/SM, 16 warps).
//  K2: one CTA/segment, bounds read directly, 6-points-per-LDG.128 gather.

#define NCP        20                     // padded Y row stride (floats)
#define GCELLS_MAX 65536
#define MAXNI      8192
__device__ float g_Y[GCELLS_MAX * NCP];   // 5.24 MB scratch (allocation-free)
__device__ int   g_bound[MAXNI + 1];

typedef unsigned long long ull;
__device__ __forceinline__ ull f2fma(ull a, ull b, ull c) {
    ull r; asm("fma.rn.f32x2 %0, %1, %2, %3;" : "=l"(r) : "l"(a), "l"(b), "l"(c));
    return r;
}
__device__ __forceinline__ ull f2pack1(float v) {
    ull r; asm("mov.b64 %0, {%1, %1};" : "=l"(r) : "f"(v));
    return r;
}
__device__ __forceinline__ float2 f2unpack(ull v) {
    float2 p; asm("mov.b64 {%0, %1}, %2;" : "=f"(p.x), "=f"(p.y) : "l"(v));
    return p;
}

// ================= K0: segment boundaries from sorted ids =================
__global__ void __launch_bounds__(256)
bounds_kernel(const int* __restrict__ ids, int P, int NI)
{
    const int i = blockIdx.x * blockDim.x + threadIdx.x;
    if (i >= P) return;
    const int cur  = __ldg(&ids[i]);
    const int prev = (i == 0) ? -1 : __ldg(&ids[i - 1]);
    for (int s = prev + 1; s <= cur; ++s) g_bound[s] = i;
    if (i == P - 1)
        for (int s = cur + 1; s <= NI; ++s) g_bound[s] = P;
}

// ===================== K1: Y[g, :] = feats[g, :] @ W  =====================
#define K1_BLOCK 128
#define K1_ROWS  256                      // thread t -> rows t, t+128
#define K1_KC    16
#define K1_FPAD  18                       // conflict-free LDS.64 in 16-lane phases

__global__ void __launch_bounds__(K1_BLOCK, 4)
project_kernel(const float* __restrict__ feats, const float* __restrict__ Wm,
               int D, int NC, int Gcells)
{
    extern __shared__ float sm[];
    float* s_f = sm;                        // [K1_ROWS][K1_FPAD]  18.4 KB
    float* s_w = sm + K1_ROWS * K1_FPAD;    // [D][NCP]            21.8 KB

    const int tid  = threadIdx.x;
    const int row0 = blockIdx.x * K1_ROWS;
    const int rows = min(K1_ROWS, Gcells - row0);

    for (int i = tid; i < D * NCP; i += K1_BLOCK) {
        const int d = i / NCP, c = i - d * NCP;
        s_w[i] = (c < NC) ? __ldg(&Wm[d * NC + c]) : 0.f;
    }

    ull accA[NCP / 2], accB[NCP / 2];
    #pragma unroll
    for (int j = 0; j < NCP / 2; ++j) { accA[j] = 0ull; accB[j] = 0ull; }

    const int rA = tid, rB = tid + K1_BLOCK;

    for (int c0 = 0; c0 < D; c0 += K1_KC) {
        const int kc = min(K1_KC, D - c0);        // 16 for D=272 (272 = 17*16)
        __syncthreads();
        for (int j = tid; j < rows * 4; j += K1_BLOCK) {
            const int r = j >> 2, k = (j & 3) << 2;
            if (k < kc) {
                const float4 v = __ldg((const float4*)
                    (feats + (size_t)(row0 + r) * D + c0 + k));
                float* dst = s_f + r * K1_FPAD + k;
                *(float2*)(dst)     = make_float2(v.x, v.y);
                *(float2*)(dst + 2) = make_float2(v.z, v.w);
            }
        }
        __syncthreads();

        const float* fa = s_f + rA * K1_FPAD;
        const float* fb = s_f + rB * K1_FPAD;
        if (kc == K1_KC) {
            #pragma unroll
            for (int kk = 0; kk < K1_KC; kk += 2) {
                const float2 pA = *(const float2*)&fa[kk];
                const float2 pB = *(const float2*)&fb[kk];
                #pragma unroll
                for (int h = 0; h < 2; ++h) {
                    const ull a = f2pack1(h ? pA.y : pA.x);
                    const ull b = f2pack1(h ? pB.y : pB.x);
                    const float4* wr = (const float4*)(s_w + (c0 + kk + h) * NCP);
                    #pragma unroll
                    for (int q = 0; q < 5; ++q) {        // 5 LDS.128 per k
                        const float4 wv = wr[q];
                        ull wp0, wp1;
                        asm("mov.b64 %0, {%1, %2};" : "=l"(wp0) : "f"(wv.x), "f"(wv.y));
                        asm("mov.b64 %0, {%1, %2};" : "=l"(wp1) : "f"(wv.z), "f"(wv.w));
                        accA[2 * q]     = f2fma(a, wp0, accA[2 * q]);
                        accA[2 * q + 1] = f2fma(a, wp1, accA[2 * q + 1]);
                        accB[2 * q]     = f2fma(b, wp0, accB[2 * q]);
                        accB[2 * q + 1] = f2fma(b, wp1, accB[2 * q + 1]);
                    }
                }
            }
        } else {
            for (int kk = 0; kk < kc; ++kk) {
                const ull a = f2pack1(fa[kk]);
                const ull b = f2pack1(fb[kk]);
                const float4* wr = (const float4*)(s_w + (c0 + kk) * NCP);
                #pragma unroll
                for (int q = 0; q < 5; ++q) {
                    const float4 wv = wr[q];
                    ull wp0, wp1;
                    asm("mov.b64 %0, {%1, %2};" : "=l"(wp0) : "f"(wv.x), "f"(wv.y));
                    asm("mov.b64 %0, {%1, %2};" : "=l"(wp1) : "f"(wv.z), "f"(wv.w));
                    accA[2 * q]     = f2fma(a, wp0, accA[2 * q]);
                    accA[2 * q + 1] = f2fma(a, wp1, accA[2 * q + 1]);
                    accB[2 * q]     = f2fma(b, wp0, accB[2 * q]);
                    accB[2 * q + 1] = f2fma(b, wp1, accB[2 * q + 1]);
                }
            }
        }
    }

    #pragma unroll 2
    for (int h = 0; h < 2; ++h) {
        const int r = row0 + (h ? rB : rA);
        if (r < Gcells) {
            const ull* acc = h ? accB : accA;
            float4* yr = (float4*)(g_Y + (size_t)r * NCP);
            #pragma unroll
            for (int j = 0; j < NCP / 4; ++j) {
                const float2 e = f2unpack(acc[2 * j]);
                const float2 o = f2unpack(acc[2 * j + 1]);
                yr[j] = make_float4(e.x, e.y, o.x, o.y);
            }
        }
    }
}

// ============ K2: out[s] = sigmoid(mean_{p in seg s} Y[idx_p] + b) ============
#define K2_BLOCK 256                      // 8 warps

__global__ void __launch_bounds__(K2_BLOCK)
pool_kernel(const float* __restrict__ bias, const int* __restrict__ point_idx,
            float* __restrict__ out, int NC)
{
    __shared__ int    s_i[K2_BLOCK];
    __shared__ float4 s_red[8][32];

    const int tid = threadIdx.x, lane = tid & 31, w = tid >> 5;
    const int seg = blockIdx.x;

    const int start = __ldg(&g_bound[seg]);
    const int end   = __ldg(&g_bound[seg + 1]);
    const int cnt   = end - start;

    // lane -> (point-sub, float4 piece): 6 points per warp LDG.128
    const int  psub  = lane / 5;           // 0..6 (6 -> inactive)
    const int  piece = lane - psub * 5;    // 0..4
    const bool gact  = (psub < 6);
    float4 acc = make_float4(0.f, 0.f, 0.f, 0.f);

    for (int base = start; base < end; base += K2_BLOCK) {
        const int n = min(K2_BLOCK, end - base);
        if (tid < n) s_i[tid] = __ldg(&point_idx[base + tid]);
        __syncthreads();
        if (gact) {
            #pragma unroll 2
            for (int i = w * 6 + psub; i < n; i += 48) {
                const int idx = s_i[i];
                const float4 v = __ldg((const float4*)g_Y + (size_t)idx * 5 + piece);
                acc.x += v.x; acc.y += v.y; acc.z += v.z; acc.w += v.w;
            }
        }
        __syncthreads();
    }

    s_red[w][lane] = gact ? acc : make_float4(0.f, 0.f, 0.f, 0.f);
    __syncthreads();

    if (tid < NC) {
        const int pc = tid >> 2, comp = tid & 3;
        float s = 0.f;
        #pragma unroll
        for (int w2 = 0; w2 < 8; ++w2)
            #pragma unroll
            for (int sub = 0; sub < 6; ++sub)
                s += ((const float*)&s_red[w2][sub * 5 + pc])[comp];
        const float x = s / (float)max(cnt, 1) + __ldg(&bias[tid]);
        out[(size_t)seg * NC + tid] = 1.0f / (1.0f + __expf(-x));
    }
}

extern "C" void kernel_launch(void* const* d_in, const int* in_sizes, int n_in,
                              void* d_out, int out_size)
{
    const float* feats       = (const float*)d_in[0];
    const float* Wm          = (const float*)d_in[1];
    const float* bias        = (const float*)d_in[2];
    const int*   point_idx   = (const int*)  d_in[3];
    const int*   segment_ids = (const int*)  d_in[4];
    float*       out         = (float*)      d_out;

    const int NC     = in_sizes[2];              // 19
    const int D      = in_sizes[1] / NC;         // 272
    const int P      = in_sizes[3];              // 524288
    const int NI     = out_size / NC;            // 4096
    const int Gcells = in_sizes[0] / D;          // 65536

    const int k1_smem = (K1_ROWS * K1_FPAD + D * NCP) * (int)sizeof(float);
    static int attr_done = 0;
    if (!attr_done) {
        cudaFuncSetAttribute(project_kernel,
                             cudaFuncAttributeMaxDynamicSharedMemorySize, k1_smem);
        attr_done = 1;
    }

    bounds_kernel<<<(P + 255) / 256, 256>>>(segment_ids, P, NI);
    project_kernel<<<(Gcells + K1_ROWS - 1) / K1_ROWS, K1_BLOCK, k1_smem>>>(
        feats, Wm, D, NC, Gcells);
    pool_kernel<<<NI, K2_BLOCK>>>(bias, point_idx, out, NC);
}